// round 4
// baseline (speedup 1.0000x reference)
#include <cuda_runtime.h>

#define B_  2
#define T_  2048
#define D_  2048
#define H_  16
#define HD_ 128

// Scratch (no cudaMalloc allowed): QKV projection output + attention output
__device__ float g_qkv[(size_t)B_ * T_ * 3 * D_];   // [B,T,3D]  ~100.7 MB
__device__ float g_att[(size_t)B_ * T_ * D_];       // [B,T,D]   ~33.6 MB

// ---------------------------------------------------------------------------
// NT SGEMM: C[M,N] = A[M,K] @ Bw[N,K]^T (+ bias[N])
// 128x128 block tile, BK=16, 256 threads, 8x8 microtile (4+4 split rows/cols)
// ---------------------------------------------------------------------------
template <bool BIAS>
__global__ __launch_bounds__(256)
void sgemm_nt(const float* __restrict__ A, const float* __restrict__ Bw,
              const float* __restrict__ bias, float* __restrict__ C,
              int M, int N, int K)
{
    __shared__ float As[16 * 132];   // [k][m], padded rows
    __shared__ float Bs[16 * 132];   // [k][n], padded rows

    const int tid = threadIdx.x;
    const int tx  = tid & 15;        // column group
    const int ty  = tid >> 4;        // row group
    const int m0  = blockIdx.y * 128;
    const int n0  = blockIdx.x * 128;

    const float* Ab = A  + (size_t)m0 * K;
    const float* Bb = Bw + (size_t)n0 * K;

    float acc[8][8];
#pragma unroll
    for (int i = 0; i < 8; i++)
#pragma unroll
        for (int j = 0; j < 8; j++) acc[i][j] = 0.f;

    for (int k0 = 0; k0 < K; k0 += 16) {
        __syncthreads();
        // cooperative load: 128 rows x 16 k each for A and B tiles
#pragma unroll
        for (int u = 0; u < 2; u++) {
            int idx = tid + u * 256;        // 0..511 float4 slots
            int row = idx >> 2;             // 0..127
            int c4  = (idx & 3) * 4;        // k offset 0,4,8,12
            float4 a4 = *(const float4*)(Ab + (size_t)row * K + k0 + c4);
            float4 b4 = *(const float4*)(Bb + (size_t)row * K + k0 + c4);
            As[(c4 + 0) * 132 + row] = a4.x;
            As[(c4 + 1) * 132 + row] = a4.y;
            As[(c4 + 2) * 132 + row] = a4.z;
            As[(c4 + 3) * 132 + row] = a4.w;
            Bs[(c4 + 0) * 132 + row] = b4.x;
            Bs[(c4 + 1) * 132 + row] = b4.y;
            Bs[(c4 + 2) * 132 + row] = b4.z;
            Bs[(c4 + 3) * 132 + row] = b4.w;
        }
        __syncthreads();

#pragma unroll
        for (int k = 0; k < 16; k++) {
            float4 a0 = *(const float4*)(As + k * 132 + ty * 4);
            float4 a1 = *(const float4*)(As + k * 132 + 64 + ty * 4);
            float4 b0 = *(const float4*)(Bs + k * 132 + tx * 4);
            float4 b1 = *(const float4*)(Bs + k * 132 + 64 + tx * 4);
            float av[8] = {a0.x, a0.y, a0.z, a0.w, a1.x, a1.y, a1.z, a1.w};
            float bv[8] = {b0.x, b0.y, b0.z, b0.w, b1.x, b1.y, b1.z, b1.w};
#pragma unroll
            for (int i = 0; i < 8; i++)
#pragma unroll
                for (int j = 0; j < 8; j++) acc[i][j] += av[i] * bv[j];
        }
    }

#pragma unroll
    for (int i = 0; i < 8; i++) {
        int m = m0 + ((i < 4) ? (ty * 4 + i) : (64 + ty * 4 + i - 4));
        float4 r0 = make_float4(acc[i][0], acc[i][1], acc[i][2], acc[i][3]);
        float4 r1 = make_float4(acc[i][4], acc[i][5], acc[i][6], acc[i][7]);
        if (BIAS) {
            const float* bp0 = bias + n0 + tx * 4;
            const float* bp1 = bias + n0 + 64 + tx * 4;
            r0.x += bp0[0]; r0.y += bp0[1]; r0.z += bp0[2]; r0.w += bp0[3];
            r1.x += bp1[0]; r1.y += bp1[1]; r1.z += bp1[2]; r1.w += bp1[3];
        }
        *(float4*)(C + (size_t)m * N + n0 + tx * 4)      = r0;
        *(float4*)(C + (size_t)m * N + n0 + 64 + tx * 4) = r1;
    }
}

// ---------------------------------------------------------------------------
// Causal flash attention, fp32. One block = 128 q rows of one (b,h).
// One thread per q row. K/V tiles of 32 rows streamed through smem.
// All hot K/V smem reads are uniform-address broadcasts (conflict-free);
// per-thread q reads use stride-132 rows (optimal 4-phase LDS.128).
// ---------------------------------------------------------------------------
__global__ __launch_bounds__(128)
void flash_attn(const float* __restrict__ qkv, float* __restrict__ out)
{
    extern __shared__ float sm[];
    float* qs = sm;                   // [128][132]
    float* ks = qs + 128 * 132;       // [ 32][132]
    float* vs = ks + 32 * 132;        // [ 32][132]
    float* ps = vs + 32 * 132;        // [128][ 33]  private p spill rows

    const int qb = blockIdx.x;        // q tile index (0..15)
    const int bh = blockIdx.y;        // b*H + h
    const int b  = bh >> 4;
    const int h  = bh & 15;
    const int t  = threadIdx.x;       // 0..127
    const int r  = qb * 128 + t;      // this thread's q row

    const size_t base = (size_t)b * T_ * 3 * D_;
    const float* qg = qkv + base +             (size_t)h * HD_;
    const float* kg = qkv + base + D_ +        (size_t)h * HD_;
    const float* vg = qkv + base + 2 * D_ +    (size_t)h * HD_;

    // load Q tile (128 x 128), coalesced, swizzle-free padded rows
#pragma unroll 4
    for (int i = 0; i < 32; i++) {
        int idx = t + i * 128;
        int row = idx >> 5;
        int c4  = (idx & 31) * 4;
        *(float4*)(qs + row * 132 + c4) =
            *(const float4*)(qg + (size_t)(qb * 128 + row) * (3 * D_) + c4);
    }

    float m = -1e30f, l = 0.f;
    float4 o[32];
#pragma unroll
    for (int i = 0; i < 32; i++) o[i] = make_float4(0.f, 0.f, 0.f, 0.f);

    const int ntiles = qb * 4 + 4;    // causal: only K rows <= qb*128+127
    for (int kb = 0; kb < ntiles; kb++) {
        __syncthreads();
        // load K,V tiles (32 x 128 each), coalesced
#pragma unroll
        for (int i = 0; i < 8; i++) {
            int idx = t + i * 128;
            int row = idx >> 5;
            int c4  = (idx & 31) * 4;
            size_t goff = (size_t)(kb * 32 + row) * (3 * D_) + c4;
            *(float4*)(ks + row * 132 + c4) = *(const float4*)(kg + goff);
            *(float4*)(vs + row * 132 + c4) = *(const float4*)(vg + goff);
        }
        __syncthreads();

        // S = q . k  (32 scores per thread)
        float s[32];
#pragma unroll
        for (int j = 0; j < 32; j++) s[j] = 0.f;
#pragma unroll 2
        for (int i = 0; i < 32; i++) {
            float4 q4 = *(const float4*)(qs + t * 132 + i * 4);
#pragma unroll
            for (int j = 0; j < 32; j++) {
                float4 k4 = *(const float4*)(ks + j * 132 + i * 4);  // broadcast
                s[j] += q4.x * k4.x; s[j] += q4.y * k4.y;
                s[j] += q4.z * k4.z; s[j] += q4.w * k4.w;
            }
        }

        // online softmax update
        const float scale = 0.08838834764831845f;   // 1/sqrt(128)
        const int kbase = kb * 32;
        float mt = m;
#pragma unroll
        for (int j = 0; j < 32; j++) {
            s[j] = (kbase + j <= r) ? s[j] * scale : -1e30f;
            mt = fmaxf(mt, s[j]);
        }
        float alpha = __expf(m - mt);
        m = mt;
        float psum = 0.f;
#pragma unroll
        for (int j = 0; j < 32; j++) {
            float p = __expf(s[j] - mt);
            ps[t * 33 + j] = p;       // private row: no sync needed
            psum += p;
        }
        l = l * alpha + psum;
#pragma unroll
        for (int i = 0; i < 32; i++) {
            o[i].x *= alpha; o[i].y *= alpha; o[i].z *= alpha; o[i].w *= alpha;
        }

        // O += P @ V
#pragma unroll 2
        for (int j = 0; j < 32; j++) {
            float p = ps[t * 33 + j];
#pragma unroll
            for (int i = 0; i < 32; i++) {
                float4 v4 = *(const float4*)(vs + j * 132 + i * 4);  // broadcast
                o[i].x += p * v4.x; o[i].y += p * v4.y;
                o[i].z += p * v4.z; o[i].w += p * v4.w;
            }
        }
    }

    // normalize + write [B,T,D] (already un-transposed layout)
    float inv = 1.0f / l;
    float* og = out + ((size_t)b * T_ + r) * D_ + h * HD_;
#pragma unroll
    for (int i = 0; i < 32; i++) {
        float4 w = o[i];
        w.x *= inv; w.y *= inv; w.z *= inv; w.w *= inv;
        *(float4*)(og + i * 4) = w;
    }
}

// ---------------------------------------------------------------------------
extern "C" void kernel_launch(void* const* d_in, const int* in_sizes, int n_in,
                              void* d_out, int out_size)
{
    (void)in_sizes; (void)n_in; (void)out_size;
    const float* x    = (const float*)d_in[0];   // [B,T,D]
    // d_in[1] = causal_mask (handled analytically)
    const float* wqkv = (const float*)d_in[2];   // [3D,D]
    const float* wout = (const float*)d_in[3];   // [D,D]
    const float* bout = (const float*)d_in[4];   // [D]
    float* outp = (float*)d_out;                 // [B,T,D] fp32

    float *qkv_p, *att_p;
    cudaGetSymbolAddress((void**)&qkv_p, g_qkv);
    cudaGetSymbolAddress((void**)&att_p, g_att);

    // 1) QKV projection: [4096,2048] x [6144,2048]^T
    dim3 g1((3 * D_) / 128, (B_ * T_) / 128);
    sgemm_nt<false><<<g1, 256>>>(x, wqkv, nullptr, qkv_p, B_ * T_, 3 * D_, D_);

    // 2) causal flash attention
    const int SMEM = (128 * 132 + 32 * 132 + 32 * 132 + 128 * 33) * 4; // 118272 B
    cudaFuncSetAttribute(flash_attn,
                         cudaFuncAttributeMaxDynamicSharedMemorySize, SMEM);
    dim3 g2(T_ / 128, B_ * H_);
    flash_attn<<<g2, 128, SMEM>>>(qkv_p, att_p);

    // 3) output projection + bias: [4096,2048] x [2048,2048]^T
    dim3 g3(D_ / 128, (B_ * T_) / 128);
    sgemm_nt<true><<<g3, 256>>>(att_p, wout, bout, outp, B_ * T_, D_, D_);
}

// round 6
// speedup vs baseline: 1.5771x; 1.5771x over previous
#include <cuda_runtime.h>
#include <cuda_bf16.h>
#include <cstdint>

#define B_  2
#define T_  2048
#define D_  2048
#define H_  16
#define HD_ 128

// Scratch (no cudaMalloc allowed)
__device__ float g_qkv[(size_t)B_ * T_ * 3 * D_];   // [B,T,3D]
__device__ float g_att[(size_t)B_ * T_ * D_];       // [B,T,D]

// ============================================================================
// bf16x3 NT GEMM on the legacy mma.sync (HMMA) path — compiles at plain sm_103.
// C[M,N] = A[M,K] @ Bw[N,K]^T (+ bias). Split a = ah + al (bf16 each);
// acc += ah*bh + ah*bl + al*bh  (residual al*bl ~ 2^-18, negligible).
//
// CTA tile 256x128, 8 warps (warp grid 4m x 2n), warp tile 64x64, K-chunk 16.
// smem: double-buffered; rows padded to 24 bf16 (48B) -> conflict-free LDS.
// ============================================================================
#define KC      16
#define AROW_P  24          // padded row stride in bf16 (48 B)
#define A_SUB   (256 * AROW_P)              // bf16 elems per A sub-tile (hi or lo)
#define B_SUB   (128 * AROW_P)
#define STAGE_ELEMS (2 * A_SUB + 2 * B_SUB) // hi+lo for A and B
#define GEMM_SMEM_BYTES (2 * STAGE_ELEMS * 2)  // 2 stages * bf16

__device__ __forceinline__ void mma16816(float* c, const uint32_t* a, const uint32_t* b) {
    asm volatile(
        "mma.sync.aligned.m16n8k16.row.col.f32.bf16.bf16.f32 "
        "{%0,%1,%2,%3}, {%4,%5,%6,%7}, {%8,%9}, {%0,%1,%2,%3};"
        : "+f"(c[0]), "+f"(c[1]), "+f"(c[2]), "+f"(c[3])
        : "r"(a[0]), "r"(a[1]), "r"(a[2]), "r"(a[3]), "r"(b[0]), "r"(b[1]));
}

__device__ __forceinline__ uint32_t bf2_bits(__nv_bfloat162 h) {
    uint32_t u; *reinterpret_cast<__nv_bfloat162*>(&u) = h; return u;
}

// split one float4 into hi/lo bf16 quads and store as STS.64 each
__device__ __forceinline__ void split_sts(__nv_bfloat16* hi, __nv_bfloat16* lo,
                                          int idx, float4 v) {
    __nv_bfloat162 h0 = __floats2bfloat162_rn(v.x, v.y);
    __nv_bfloat162 h1 = __floats2bfloat162_rn(v.z, v.w);
    __nv_bfloat162 l0 = __floats2bfloat162_rn(v.x - __low2float(h0),
                                              v.y - __high2float(h0));
    __nv_bfloat162 l1 = __floats2bfloat162_rn(v.z - __low2float(h1),
                                              v.w - __high2float(h1));
    uint2 hv = make_uint2(bf2_bits(h0), bf2_bits(h1));
    uint2 lv = make_uint2(bf2_bits(l0), bf2_bits(l1));
    *reinterpret_cast<uint2*>(hi + idx) = hv;
    *reinterpret_cast<uint2*>(lo + idx) = lv;
}

template <bool BIAS>
__global__ __launch_bounds__(256)
void gemm_hmma(const float* __restrict__ A, const float* __restrict__ Bw,
               const float* __restrict__ bias, float* __restrict__ C,
               int M, int N, int K)
{
    extern __shared__ __nv_bfloat16 smem[];

    const int tid = threadIdx.x;
    const int wid = tid >> 5;
    const int lid = tid & 31;
    const int gid = lid >> 2;          // group (row) in fragment
    const int tig = lid & 3;           // thread-in-group (col pair)
    const int wm  = wid >> 1;          // warp m index (0..3)
    const int wn  = wid & 1;           // warp n index (0..1)
    const int m0  = blockIdx.y * 256;
    const int n0  = blockIdx.x * 128;

    const float* Ab = A  + (size_t)m0 * K;
    const float* Bb = Bw + (size_t)n0 * K;

    // per-thread load geometry: 4 A-float4 + 2 B-float4 per K-chunk
    const int arow0 = tid >> 2;        // 0..63, +u*64
    const int ac4   = (tid & 3) * 4;   // k offset 0,4,8,12

    float acc[4][8][4];
#pragma unroll
    for (int i = 0; i < 4; i++)
#pragma unroll
        for (int j = 0; j < 8; j++)
#pragma unroll
            for (int r = 0; r < 4; r++) acc[i][j][r] = 0.f;

    const int NC = K / KC;             // 128
    float4 areg[4], breg[2];

    // ---- prologue: load + split chunk 0 into stage 0
#pragma unroll
    for (int u = 0; u < 4; u++)
        areg[u] = *(const float4*)(Ab + (size_t)(arow0 + u * 64) * K + ac4);
#pragma unroll
    for (int u = 0; u < 2; u++)
        breg[u] = *(const float4*)(Bb + (size_t)(arow0 + u * 64) * K + ac4);
    {
        __nv_bfloat16* AH = smem;
        __nv_bfloat16* AL = smem + A_SUB;
        __nv_bfloat16* BH = smem + 2 * A_SUB;
        __nv_bfloat16* BL = smem + 2 * A_SUB + B_SUB;
#pragma unroll
        for (int u = 0; u < 4; u++)
            split_sts(AH, AL, (arow0 + u * 64) * AROW_P + ac4, areg[u]);
#pragma unroll
        for (int u = 0; u < 2; u++)
            split_sts(BH, BL, (arow0 + u * 64) * AROW_P + ac4, breg[u]);
    }
    __syncthreads();

    for (int kc = 0; kc < NC; kc++) {
        const int s = kc & 1;
        const int k0n = (kc + 1) * KC;

        // issue next chunk's LDGs early (overlap with MMA)
        if (kc + 1 < NC) {
#pragma unroll
            for (int u = 0; u < 4; u++)
                areg[u] = *(const float4*)(Ab + (size_t)(arow0 + u * 64) * K + k0n + ac4);
#pragma unroll
            for (int u = 0; u < 2; u++)
                breg[u] = *(const float4*)(Bb + (size_t)(arow0 + u * 64) * K + k0n + ac4);
        }

        // ---- compute current stage
        const __nv_bfloat16* AH = smem + s * STAGE_ELEMS;
        const __nv_bfloat16* AL = AH + A_SUB;
        const __nv_bfloat16* BH = AH + 2 * A_SUB;
        const __nv_bfloat16* BL = AH + 2 * A_SUB + B_SUB;
        const int cc = tig * 2;

        uint32_t ah[4][4], al[4][4];
#pragma unroll
        for (int mt = 0; mt < 4; mt++) {
            int r0 = wm * 64 + mt * 16 + gid;
            ah[mt][0] = *(const uint32_t*)(AH + r0 * AROW_P + cc);
            ah[mt][1] = *(const uint32_t*)(AH + (r0 + 8) * AROW_P + cc);
            ah[mt][2] = *(const uint32_t*)(AH + r0 * AROW_P + cc + 8);
            ah[mt][3] = *(const uint32_t*)(AH + (r0 + 8) * AROW_P + cc + 8);
            al[mt][0] = *(const uint32_t*)(AL + r0 * AROW_P + cc);
            al[mt][1] = *(const uint32_t*)(AL + (r0 + 8) * AROW_P + cc);
            al[mt][2] = *(const uint32_t*)(AL + r0 * AROW_P + cc + 8);
            al[mt][3] = *(const uint32_t*)(AL + (r0 + 8) * AROW_P + cc + 8);
        }
#pragma unroll
        for (int nt = 0; nt < 8; nt++) {
            int rn = wn * 64 + nt * 8 + gid;
            uint32_t bh[2], bl[2];
            bh[0] = *(const uint32_t*)(BH + rn * AROW_P + cc);
            bh[1] = *(const uint32_t*)(BH + rn * AROW_P + cc + 8);
            bl[0] = *(const uint32_t*)(BL + rn * AROW_P + cc);
            bl[1] = *(const uint32_t*)(BL + rn * AROW_P + cc + 8);
#pragma unroll
            for (int mt = 0; mt < 4; mt++) {
                mma16816(acc[mt][nt], ah[mt], bh);
                mma16816(acc[mt][nt], ah[mt], bl);
                mma16816(acc[mt][nt], al[mt], bh);
            }
        }

        __syncthreads();
        if (kc + 1 < NC) {
            __nv_bfloat16* AHn = smem + (s ^ 1) * STAGE_ELEMS;
            __nv_bfloat16* ALn = AHn + A_SUB;
            __nv_bfloat16* BHn = AHn + 2 * A_SUB;
            __nv_bfloat16* BLn = AHn + 2 * A_SUB + B_SUB;
#pragma unroll
            for (int u = 0; u < 4; u++)
                split_sts(AHn, ALn, (arow0 + u * 64) * AROW_P + ac4, areg[u]);
#pragma unroll
            for (int u = 0; u < 2; u++)
                split_sts(BHn, BLn, (arow0 + u * 64) * AROW_P + ac4, breg[u]);
            __syncthreads();
        }
    }

    // ---- epilogue: direct STG.64 from accumulator fragments
#pragma unroll
    for (int mt = 0; mt < 4; mt++) {
        int m = m0 + wm * 64 + mt * 16 + gid;
#pragma unroll
        for (int nt = 0; nt < 8; nt++) {
            int n = n0 + wn * 64 + nt * 8 + tig * 2;
            float2 v0 = make_float2(acc[mt][nt][0], acc[mt][nt][1]);
            float2 v1 = make_float2(acc[mt][nt][2], acc[mt][nt][3]);
            if (BIAS) {
                float b0 = bias[n], b1 = bias[n + 1];
                v0.x += b0; v0.y += b1;
                v1.x += b0; v1.y += b1;
            }
            *(float2*)(C + (size_t)m * N + n)       = v0;
            *(float2*)(C + (size_t)(m + 8) * N + n) = v1;
        }
    }
}

// ---------------------------------------------------------------------------
// Causal flash attention, fp32 (unchanged — proven correct at R4)
// ---------------------------------------------------------------------------
__global__ __launch_bounds__(128)
void flash_attn(const float* __restrict__ qkv, float* __restrict__ out)
{
    extern __shared__ float sm[];
    float* qs = sm;                   // [128][132]
    float* ks = qs + 128 * 132;       // [ 32][132]
    float* vs = ks + 32 * 132;        // [ 32][132]
    float* ps = vs + 32 * 132;        // [128][ 33]

    const int qb = blockIdx.x;
    const int bh = blockIdx.y;
    const int b  = bh >> 4;
    const int h  = bh & 15;
    const int t  = threadIdx.x;
    const int r  = qb * 128 + t;

    const size_t base = (size_t)b * T_ * 3 * D_;
    const float* qg = qkv + base +          (size_t)h * HD_;
    const float* kg = qkv + base + D_ +     (size_t)h * HD_;
    const float* vg = qkv + base + 2 * D_ + (size_t)h * HD_;

#pragma unroll 4
    for (int i = 0; i < 32; i++) {
        int idx = t + i * 128;
        int row = idx >> 5;
        int c4  = (idx & 31) * 4;
        *(float4*)(qs + row * 132 + c4) =
            *(const float4*)(qg + (size_t)(qb * 128 + row) * (3 * D_) + c4);
    }

    float m = -1e30f, l = 0.f;
    float4 o[32];
#pragma unroll
    for (int i = 0; i < 32; i++) o[i] = make_float4(0.f, 0.f, 0.f, 0.f);

    const int ntiles = qb * 4 + 4;
    for (int kb = 0; kb < ntiles; kb++) {
        __syncthreads();
#pragma unroll
        for (int i = 0; i < 8; i++) {
            int idx = t + i * 128;
            int row = idx >> 5;
            int c4  = (idx & 31) * 4;
            size_t goff = (size_t)(kb * 32 + row) * (3 * D_) + c4;
            *(float4*)(ks + row * 132 + c4) = *(const float4*)(kg + goff);
            *(float4*)(vs + row * 132 + c4) = *(const float4*)(vg + goff);
        }
        __syncthreads();

        float s[32];
#pragma unroll
        for (int j = 0; j < 32; j++) s[j] = 0.f;
#pragma unroll 2
        for (int i = 0; i < 32; i++) {
            float4 q4 = *(const float4*)(qs + t * 132 + i * 4);
#pragma unroll
            for (int j = 0; j < 32; j++) {
                float4 k4 = *(const float4*)(ks + j * 132 + i * 4);
                s[j] += q4.x * k4.x; s[j] += q4.y * k4.y;
                s[j] += q4.z * k4.z; s[j] += q4.w * k4.w;
            }
        }

        const float scale = 0.08838834764831845f;
        const int kbase = kb * 32;
        float mt = m;
#pragma unroll
        for (int j = 0; j < 32; j++) {
            s[j] = (kbase + j <= r) ? s[j] * scale : -1e30f;
            mt = fmaxf(mt, s[j]);
        }
        float alpha = __expf(m - mt);
        m = mt;
        float psum = 0.f;
#pragma unroll
        for (int j = 0; j < 32; j++) {
            float p = __expf(s[j] - mt);
            ps[t * 33 + j] = p;
            psum += p;
        }
        l = l * alpha + psum;
#pragma unroll
        for (int i = 0; i < 32; i++) {
            o[i].x *= alpha; o[i].y *= alpha; o[i].z *= alpha; o[i].w *= alpha;
        }

#pragma unroll 2
        for (int j = 0; j < 32; j++) {
            float p = ps[t * 33 + j];
#pragma unroll
            for (int i = 0; i < 32; i++) {
                float4 v4 = *(const float4*)(vs + j * 132 + i * 4);
                o[i].x += p * v4.x; o[i].y += p * v4.y;
                o[i].z += p * v4.z; o[i].w += p * v4.w;
            }
        }
    }

    float inv = 1.0f / l;
    float* og = out + ((size_t)b * T_ + r) * D_ + h * HD_;
#pragma unroll
    for (int i = 0; i < 32; i++) {
        float4 w = o[i];
        w.x *= inv; w.y *= inv; w.z *= inv; w.w *= inv;
        *(float4*)(og + i * 4) = w;
    }
}

// ---------------------------------------------------------------------------
extern "C" void kernel_launch(void* const* d_in, const int* in_sizes, int n_in,
                              void* d_out, int out_size)
{
    (void)in_sizes; (void)n_in; (void)out_size;
    const float* x    = (const float*)d_in[0];   // [B,T,D]
    const float* wqkv = (const float*)d_in[2];   // [3D,D]
    const float* wout = (const float*)d_in[3];   // [D,D]
    const float* bout = (const float*)d_in[4];   // [D]
    float* outp = (float*)d_out;

    float *qkv_p, *att_p;
    cudaGetSymbolAddress((void**)&qkv_p, g_qkv);
    cudaGetSymbolAddress((void**)&att_p, g_att);

    cudaFuncSetAttribute(gemm_hmma<false>,
                         cudaFuncAttributeMaxDynamicSharedMemorySize, GEMM_SMEM_BYTES);
    cudaFuncSetAttribute(gemm_hmma<true>,
                         cudaFuncAttributeMaxDynamicSharedMemorySize, GEMM_SMEM_BYTES);

    // 1) QKV projection: [4096,2048] x [6144,2048]^T  (bf16x3 HMMA)
    dim3 g1((3 * D_) / 128, (B_ * T_) / 256);
    gemm_hmma<false><<<g1, 256, GEMM_SMEM_BYTES>>>(x, wqkv, nullptr, qkv_p,
                                                   B_ * T_, 3 * D_, D_);

    // 2) causal flash attention (fp32 FFMA, unchanged)
    const int ATT_SMEM = (128 * 132 + 32 * 132 + 32 * 132 + 128 * 33) * 4;
    cudaFuncSetAttribute(flash_attn,
                         cudaFuncAttributeMaxDynamicSharedMemorySize, ATT_SMEM);
    dim3 g2(T_ / 128, B_ * H_);
    flash_attn<<<g2, 128, ATT_SMEM>>>(qkv_p, att_p);

    // 3) output projection + bias: [4096,2048] x [2048,2048]^T (bf16x3 HMMA)
    dim3 g3(D_ / 128, (B_ * T_) / 256);
    gemm_hmma<true><<<g3, 256, GEMM_SMEM_BYTES>>>(att_p, wout, bout, outp,
                                                  B_ * T_, D_, D_);
}

// round 8
// speedup vs baseline: 1.6431x; 1.0419x over previous
#include <cuda_runtime.h>
#include <cuda_bf16.h>
#include <cstdint>

#define B_  2
#define T_  2048
#define D_  2048
#define H_  16
#define HD_ 128

// Scratch (no cudaMalloc allowed)
__device__ float g_qkv[(size_t)B_ * T_ * 3 * D_];   // [B,T,3D]
__device__ float g_att[(size_t)B_ * T_ * D_];       // [B,T,D]

// ============================================================================
// Common HMMA helpers
// ============================================================================
__device__ __forceinline__ void mma16816(float* c, const uint32_t* a, const uint32_t* b) {
    asm volatile(
        "mma.sync.aligned.m16n8k16.row.col.f32.bf16.bf16.f32 "
        "{%0,%1,%2,%3}, {%4,%5,%6,%7}, {%8,%9}, {%0,%1,%2,%3};"
        : "+f"(c[0]), "+f"(c[1]), "+f"(c[2]), "+f"(c[3])
        : "r"(a[0]), "r"(a[1]), "r"(a[2]), "r"(a[3]), "r"(b[0]), "r"(b[1]));
}
__device__ __forceinline__ uint32_t bf2_bits(__nv_bfloat162 h) {
    uint32_t u; *reinterpret_cast<__nv_bfloat162*>(&u) = h; return u;
}
__device__ __forceinline__ void split2(float x, float y, uint32_t& hi, uint32_t& lo) {
    __nv_bfloat162 h = __floats2bfloat162_rn(x, y);
    __nv_bfloat162 l = __floats2bfloat162_rn(x - __low2float(h), y - __high2float(h));
    hi = bf2_bits(h); lo = bf2_bits(l);
}
__device__ __forceinline__ void split4(float4 v, uint2& hi, uint2& lo) {
    __nv_bfloat162 h0 = __floats2bfloat162_rn(v.x, v.y);
    __nv_bfloat162 h1 = __floats2bfloat162_rn(v.z, v.w);
    __nv_bfloat162 l0 = __floats2bfloat162_rn(v.x - __low2float(h0), v.y - __high2float(h0));
    __nv_bfloat162 l1 = __floats2bfloat162_rn(v.z - __low2float(h1), v.w - __high2float(h1));
    hi = make_uint2(bf2_bits(h0), bf2_bits(h1));
    lo = make_uint2(bf2_bits(l0), bf2_bits(l1));
}
__device__ __forceinline__ uint32_t smem_u32_of(const void* p) {
    uint32_t a;
    asm("{ .reg .u64 t; cvta.to.shared.u64 t, %1; cvt.u32.u64 %0, t; }"
        : "=r"(a) : "l"(p));
    return a;
}
__device__ __forceinline__ void ldmx4t(uint32_t* r, uint32_t saddr) {
    asm volatile("ldmatrix.sync.aligned.m8n8.x4.trans.shared.b16 {%0,%1,%2,%3}, [%4];"
                 : "=r"(r[0]), "=r"(r[1]), "=r"(r[2]), "=r"(r[3]) : "r"(saddr));
}

// ============================================================================
// bf16x3 NT GEMM (unchanged from R6 — tensor=53%, proven 2.5e-5)
// ============================================================================
#define KC      16
#define AROW_P  24
#define A_SUB   (256 * AROW_P)
#define B_SUB   (128 * AROW_P)
#define STAGE_ELEMS (2 * A_SUB + 2 * B_SUB)
#define GEMM_SMEM_BYTES (2 * STAGE_ELEMS * 2)

__device__ __forceinline__ void split_sts(__nv_bfloat16* hi, __nv_bfloat16* lo,
                                          int idx, float4 v) {
    uint2 hv, lv;
    split4(v, hv, lv);
    *reinterpret_cast<uint2*>(hi + idx) = hv;
    *reinterpret_cast<uint2*>(lo + idx) = lv;
}

template <bool BIAS>
__global__ __launch_bounds__(256)
void gemm_hmma(const float* __restrict__ A, const float* __restrict__ Bw,
               const float* __restrict__ bias, float* __restrict__ C,
               int M, int N, int K)
{
    extern __shared__ __nv_bfloat16 smem[];

    const int tid = threadIdx.x;
    const int wid = tid >> 5;
    const int lid = tid & 31;
    const int gid = lid >> 2;
    const int tig = lid & 3;
    const int wm  = wid >> 1;
    const int wn  = wid & 1;
    const int m0  = blockIdx.y * 256;
    const int n0  = blockIdx.x * 128;

    const float* Ab = A  + (size_t)m0 * K;
    const float* Bb = Bw + (size_t)n0 * K;

    const int arow0 = tid >> 2;
    const int ac4   = (tid & 3) * 4;

    float acc[4][8][4];
#pragma unroll
    for (int i = 0; i < 4; i++)
#pragma unroll
        for (int j = 0; j < 8; j++)
#pragma unroll
            for (int r = 0; r < 4; r++) acc[i][j][r] = 0.f;

    const int NC = K / KC;
    float4 areg[4], breg[2];

#pragma unroll
    for (int u = 0; u < 4; u++)
        areg[u] = *(const float4*)(Ab + (size_t)(arow0 + u * 64) * K + ac4);
#pragma unroll
    for (int u = 0; u < 2; u++)
        breg[u] = *(const float4*)(Bb + (size_t)(arow0 + u * 64) * K + ac4);
    {
        __nv_bfloat16* AH = smem;
        __nv_bfloat16* AL = smem + A_SUB;
        __nv_bfloat16* BH = smem + 2 * A_SUB;
        __nv_bfloat16* BL = smem + 2 * A_SUB + B_SUB;
#pragma unroll
        for (int u = 0; u < 4; u++)
            split_sts(AH, AL, (arow0 + u * 64) * AROW_P + ac4, areg[u]);
#pragma unroll
        for (int u = 0; u < 2; u++)
            split_sts(BH, BL, (arow0 + u * 64) * AROW_P + ac4, breg[u]);
    }
    __syncthreads();

    for (int kc = 0; kc < NC; kc++) {
        const int s = kc & 1;
        const int k0n = (kc + 1) * KC;

        if (kc + 1 < NC) {
#pragma unroll
            for (int u = 0; u < 4; u++)
                areg[u] = *(const float4*)(Ab + (size_t)(arow0 + u * 64) * K + k0n + ac4);
#pragma unroll
            for (int u = 0; u < 2; u++)
                breg[u] = *(const float4*)(Bb + (size_t)(arow0 + u * 64) * K + k0n + ac4);
        }

        const __nv_bfloat16* AH = smem + s * STAGE_ELEMS;
        const __nv_bfloat16* AL = AH + A_SUB;
        const __nv_bfloat16* BH = AH + 2 * A_SUB;
        const __nv_bfloat16* BL = AH + 2 * A_SUB + B_SUB;
        const int cc = tig * 2;

        uint32_t ah[4][4], al[4][4];
#pragma unroll
        for (int mt = 0; mt < 4; mt++) {
            int r0 = wm * 64 + mt * 16 + gid;
            ah[mt][0] = *(const uint32_t*)(AH + r0 * AROW_P + cc);
            ah[mt][1] = *(const uint32_t*)(AH + (r0 + 8) * AROW_P + cc);
            ah[mt][2] = *(const uint32_t*)(AH + r0 * AROW_P + cc + 8);
            ah[mt][3] = *(const uint32_t*)(AH + (r0 + 8) * AROW_P + cc + 8);
            al[mt][0] = *(const uint32_t*)(AL + r0 * AROW_P + cc);
            al[mt][1] = *(const uint32_t*)(AL + (r0 + 8) * AROW_P + cc);
            al[mt][2] = *(const uint32_t*)(AL + r0 * AROW_P + cc + 8);
            al[mt][3] = *(const uint32_t*)(AL + (r0 + 8) * AROW_P + cc + 8);
        }
#pragma unroll
        for (int nt = 0; nt < 8; nt++) {
            int rn = wn * 64 + nt * 8 + gid;
            uint32_t bh[2], bl[2];
            bh[0] = *(const uint32_t*)(BH + rn * AROW_P + cc);
            bh[1] = *(const uint32_t*)(BH + rn * AROW_P + cc + 8);
            bl[0] = *(const uint32_t*)(BL + rn * AROW_P + cc);
            bl[1] = *(const uint32_t*)(BL + rn * AROW_P + cc + 8);
#pragma unroll
            for (int mt = 0; mt < 4; mt++) {
                mma16816(acc[mt][nt], ah[mt], bh);
                mma16816(acc[mt][nt], ah[mt], bl);
                mma16816(acc[mt][nt], al[mt], bh);
            }
        }

        __syncthreads();
        if (kc + 1 < NC) {
            __nv_bfloat16* AHn = smem + (s ^ 1) * STAGE_ELEMS;
            __nv_bfloat16* ALn = AHn + A_SUB;
            __nv_bfloat16* BHn = AHn + 2 * A_SUB;
            __nv_bfloat16* BLn = AHn + 2 * A_SUB + B_SUB;
#pragma unroll
            for (int u = 0; u < 4; u++)
                split_sts(AHn, ALn, (arow0 + u * 64) * AROW_P + ac4, areg[u]);
#pragma unroll
            for (int u = 0; u < 2; u++)
                split_sts(BHn, BLn, (arow0 + u * 64) * AROW_P + ac4, breg[u]);
            __syncthreads();
        }
    }

#pragma unroll
    for (int mt = 0; mt < 4; mt++) {
        int m = m0 + wm * 64 + mt * 16 + gid;
#pragma unroll
        for (int nt = 0; nt < 8; nt++) {
            int n = n0 + wn * 64 + nt * 8 + tig * 2;
            float2 v0 = make_float2(acc[mt][nt][0], acc[mt][nt][1]);
            float2 v1 = make_float2(acc[mt][nt][2], acc[mt][nt][3]);
            if (BIAS) {
                float b0 = bias[n], b1 = bias[n + 1];
                v0.x += b0; v0.y += b1;
                v1.x += b0; v1.y += b1;
            }
            *(float2*)(C + (size_t)m * N + n)       = v0;
            *(float2*)(C + (size_t)(m + 8) * N + n) = v1;
        }
    }
}

// ============================================================================
// HMMA causal flash attention (bf16x3 both GEMMs)
// CTA: 8 warps, 128 q-rows of one (b,h). Warp w owns rows w*16 + {gid, gid+8}.
// Q fragments register-resident (scale folded). K/V 64-key tiles in smem,
// bf16 hi/lo, row stride 152 (conflict-free S b-frag reads).
// PV B-fragments via ldmatrix.x4.trans on naturally-stored V.
// ============================================================================
#define AST 152                         // bf16 row stride
#define ATT_SMEM_BYTES (4 * 64 * AST * 2)   // KH,KL,VH,VL = 77824 B

__global__ __launch_bounds__(256)
void flash_hmma(const float* __restrict__ qkv, float* __restrict__ out)
{
    extern __shared__ __nv_bfloat16 asm_[];
    __nv_bfloat16* KH = asm_;
    __nv_bfloat16* KL = KH + 64 * AST;
    __nv_bfloat16* VH = KL + 64 * AST;
    __nv_bfloat16* VL = VH + 64 * AST;

    const int qb  = blockIdx.x;
    const int bh  = blockIdx.y;
    const int b   = bh >> 4;
    const int h   = bh & 15;
    const int tid = threadIdx.x;
    const int wid = tid >> 5;
    const int lid = tid & 31;
    const int gid = lid >> 2;
    const int tig = lid & 3;

    const size_t base = (size_t)b * T_ * 3 * D_;
    const float* qg = qkv + base +          (size_t)h * HD_;
    const float* kg = qkv + base + D_ +     (size_t)h * HD_;
    const float* vg = qkv + base + 2 * D_ + (size_t)h * HD_;

    // ---- Q fragments, register resident, scale folded pre-split
    const float scale = 0.08838834764831845f;   // 1/sqrt(128)
    const int r0 = qb * 128 + wid * 16 + gid;   // this lane's row pair: r0, r0+8
    uint32_t qh[8][4], ql[8][4];
    {
        const float* q0 = qg + (size_t)r0 * (3 * D_);
        const float* q1 = qg + (size_t)(r0 + 8) * (3 * D_);
#pragma unroll
        for (int kc = 0; kc < 8; kc++) {
            float2 v0 = *(const float2*)(q0 + kc * 16 + 2 * tig);
            float2 v1 = *(const float2*)(q1 + kc * 16 + 2 * tig);
            float2 v2 = *(const float2*)(q0 + kc * 16 + 2 * tig + 8);
            float2 v3 = *(const float2*)(q1 + kc * 16 + 2 * tig + 8);
            split2(v0.x * scale, v0.y * scale, qh[kc][0], ql[kc][0]);
            split2(v1.x * scale, v1.y * scale, qh[kc][1], ql[kc][1]);
            split2(v2.x * scale, v2.y * scale, qh[kc][2], ql[kc][2]);
            split2(v3.x * scale, v3.y * scale, qh[kc][3], ql[kc][3]);
        }
    }

    float m0 = -1e30f, m1 = -1e30f, l0 = 0.f, l1 = 0.f;
    float o[16][4];
#pragma unroll
    for (int i = 0; i < 16; i++)
#pragma unroll
        for (int r = 0; r < 4; r++) o[i][r] = 0.f;

    // per-lane ldmatrix static offset (bytes): key=(lid&15), hd=8*(lid>>4)
    const uint32_t vbase_h = smem_u32_of(VH);
    const uint32_t vbase_l = smem_u32_of(VL);
    const uint32_t voff = (uint32_t)(((lid & 15) * AST + (lid >> 4) * 8) * 2);

    // K/V loader geometry: key = wid*8 + (tid&7); col-slot = (tid>>3)&3 (+4u)
    const int lkey = wid * 8 + (tid & 7);
    const int lcs0 = (tid >> 3) & 3;

    const int ntiles = 2 * qb + 2;
    for (int kb = 0; kb < ntiles; kb++) {
        __syncthreads();
        {
            const float* kr = kg + (size_t)(kb * 64 + lkey) * (3 * D_);
            const float* vr = vg + (size_t)(kb * 64 + lkey) * (3 * D_);
#pragma unroll
            for (int u = 0; u < 8; u++) {
                int cs = lcs0 + u * 4;          // 0..31 (float4 slot)
                float4 k4 = *(const float4*)(kr + cs * 4);
                float4 v4 = *(const float4*)(vr + cs * 4);
                uint2 hi, lo;
                split4(k4, hi, lo);
                *(uint2*)(KH + lkey * AST + cs * 4) = hi;
                *(uint2*)(KL + lkey * AST + cs * 4) = lo;
                split4(v4, hi, lo);
                *(uint2*)(VH + lkey * AST + cs * 4) = hi;
                *(uint2*)(VL + lkey * AST + cs * 4) = lo;
            }
        }
        __syncthreads();

        // ---- S = Q K^T (scaled), 8 n-tiles of 8 keys
        float s[8][4];
#pragma unroll
        for (int nt = 0; nt < 8; nt++)
#pragma unroll
            for (int r = 0; r < 4; r++) s[nt][r] = 0.f;

#pragma unroll
        for (int kc = 0; kc < 8; kc++) {
#pragma unroll
            for (int nt = 0; nt < 8; nt++) {
                const __nv_bfloat16* kph = KH + (nt * 8 + gid) * AST + kc * 16 + 2 * tig;
                const __nv_bfloat16* kpl = KL + (nt * 8 + gid) * AST + kc * 16 + 2 * tig;
                uint32_t bh[2], bl[2];
                bh[0] = *(const uint32_t*)(kph);
                bh[1] = *(const uint32_t*)(kph + 8);
                bl[0] = *(const uint32_t*)(kpl);
                bl[1] = *(const uint32_t*)(kpl + 8);
                mma16816(s[nt], qh[kc], bh);
                mma16816(s[nt], qh[kc], bl);
                mma16816(s[nt], ql[kc], bh);
            }
        }

        // ---- causal mask (warp-uniform branch)
        if (kb * 64 + 63 > qb * 128 + wid * 16) {
            const int rr0 = r0, rr1 = r0 + 8;
#pragma unroll
            for (int nt = 0; nt < 8; nt++) {
                int c0 = kb * 64 + nt * 8 + 2 * tig;
                int c1 = c0 + 1;
                if (c0 > rr0) s[nt][0] = -1e30f;
                if (c1 > rr0) s[nt][1] = -1e30f;
                if (c0 > rr1) s[nt][2] = -1e30f;
                if (c1 > rr1) s[nt][3] = -1e30f;
            }
        }

        // ---- online softmax (fragment-level; quad shfl reductions)
        float mx0 = -1e30f, mx1 = -1e30f;
#pragma unroll
        for (int nt = 0; nt < 8; nt++) {
            mx0 = fmaxf(mx0, fmaxf(s[nt][0], s[nt][1]));
            mx1 = fmaxf(mx1, fmaxf(s[nt][2], s[nt][3]));
        }
        mx0 = fmaxf(mx0, __shfl_xor_sync(0xFFFFFFFF, mx0, 1));
        mx0 = fmaxf(mx0, __shfl_xor_sync(0xFFFFFFFF, mx0, 2));
        mx1 = fmaxf(mx1, __shfl_xor_sync(0xFFFFFFFF, mx1, 1));
        mx1 = fmaxf(mx1, __shfl_xor_sync(0xFFFFFFFF, mx1, 2));
        float mn0 = fmaxf(m0, mx0), mn1 = fmaxf(m1, mx1);
        float a0 = __expf(m0 - mn0), a1 = __expf(m1 - mn1);
        m0 = mn0; m1 = mn1;

        float ps0 = 0.f, ps1 = 0.f;
#pragma unroll
        for (int nt = 0; nt < 8; nt++) {
            s[nt][0] = __expf(s[nt][0] - mn0); ps0 += s[nt][0];
            s[nt][1] = __expf(s[nt][1] - mn0); ps0 += s[nt][1];
            s[nt][2] = __expf(s[nt][2] - mn1); ps1 += s[nt][2];
            s[nt][3] = __expf(s[nt][3] - mn1); ps1 += s[nt][3];
        }
        ps0 += __shfl_xor_sync(0xFFFFFFFF, ps0, 1);
        ps0 += __shfl_xor_sync(0xFFFFFFFF, ps0, 2);
        ps1 += __shfl_xor_sync(0xFFFFFFFF, ps1, 1);
        ps1 += __shfl_xor_sync(0xFFFFFFFF, ps1, 2);
        l0 = l0 * a0 + ps0;
        l1 = l1 * a1 + ps1;

#pragma unroll
        for (int nt = 0; nt < 16; nt++) {
            o[nt][0] *= a0; o[nt][1] *= a0;
            o[nt][2] *= a1; o[nt][3] *= a1;
        }

        // ---- O += P V   (P a-frags from S accs; V b-frags via ldmatrix.trans)
#pragma unroll
        for (int kt = 0; kt < 4; kt++) {
            uint32_t aph[4], apl[4];
            split2(s[2 * kt][0],     s[2 * kt][1],     aph[0], apl[0]);
            split2(s[2 * kt][2],     s[2 * kt][3],     aph[1], apl[1]);
            split2(s[2 * kt + 1][0], s[2 * kt + 1][1], aph[2], apl[2]);
            split2(s[2 * kt + 1][2], s[2 * kt + 1][3], aph[3], apl[3]);
            const uint32_t ktoff = (uint32_t)(kt * 16 * AST * 2);
#pragma unroll
            for (int ntp = 0; ntp < 8; ntp++) {
                uint32_t vh4[4], vl4[4];
                uint32_t off = ktoff + (uint32_t)(ntp * 32) + voff;
                ldmx4t(vh4, vbase_h + off);
                ldmx4t(vl4, vbase_l + off);
                mma16816(o[2 * ntp],     aph, vh4);
                mma16816(o[2 * ntp],     aph, vl4);
                mma16816(o[2 * ntp],     apl, vh4);
                mma16816(o[2 * ntp + 1], aph, vh4 + 2);
                mma16816(o[2 * ntp + 1], aph, vl4 + 2);
                mma16816(o[2 * ntp + 1], apl, vh4 + 2);
            }
        }
    }

    // ---- normalize + write
    float il0 = 1.f / l0, il1 = 1.f / l1;
    float* o0 = out + ((size_t)b * T_ + r0) * D_ + h * HD_;
    float* o1 = out + ((size_t)b * T_ + r0 + 8) * D_ + h * HD_;
#pragma unroll
    for (int nt = 0; nt < 16; nt++) {
        *(float2*)(o0 + nt * 8 + 2 * tig) = make_float2(o[nt][0] * il0, o[nt][1] * il0);
        *(float2*)(o1 + nt * 8 + 2 * tig) = make_float2(o[nt][2] * il1, o[nt][3] * il1);
    }
}

// ---------------------------------------------------------------------------
extern "C" void kernel_launch(void* const* d_in, const int* in_sizes, int n_in,
                              void* d_out, int out_size)
{
    (void)in_sizes; (void)n_in; (void)out_size;
    const float* x    = (const float*)d_in[0];   // [B,T,D]
    const float* wqkv = (const float*)d_in[2];   // [3D,D]
    const float* wout = (const float*)d_in[3];   // [D,D]
    const float* bout = (const float*)d_in[4];   // [D]
    float* outp = (float*)d_out;

    float *qkv_p, *att_p;
    cudaGetSymbolAddress((void**)&qkv_p, g_qkv);
    cudaGetSymbolAddress((void**)&att_p, g_att);

    cudaFuncSetAttribute(gemm_hmma<false>,
                         cudaFuncAttributeMaxDynamicSharedMemorySize, GEMM_SMEM_BYTES);
    cudaFuncSetAttribute(gemm_hmma<true>,
                         cudaFuncAttributeMaxDynamicSharedMemorySize, GEMM_SMEM_BYTES);
    cudaFuncSetAttribute(flash_hmma,
                         cudaFuncAttributeMaxDynamicSharedMemorySize, ATT_SMEM_BYTES);

    // 1) QKV projection: [4096,2048] x [6144,2048]^T  (bf16x3 HMMA)
    dim3 g1((3 * D_) / 128, (B_ * T_) / 256);
    gemm_hmma<false><<<g1, 256, GEMM_SMEM_BYTES>>>(x, wqkv, nullptr, qkv_p,
                                                   B_ * T_, 3 * D_, D_);

    // 2) causal flash attention (bf16x3 HMMA)
    dim3 g2(T_ / 128, B_ * H_);
    flash_hmma<<<g2, 256, ATT_SMEM_BYTES>>>(qkv_p, att_p);

    // 3) output projection + bias: [4096,2048] x [2048,2048]^T (bf16x3 HMMA)
    dim3 g3(D_ / 128, (B_ * T_) / 256);
    gemm_hmma<true><<<g3, 256, GEMM_SMEM_BYTES>>>(att_p, wout, bout, outp,
                                                  B_ * T_, D_, D_);
}

// round 9
// speedup vs baseline: 2.7507x; 1.6741x over previous
#include <cuda_runtime.h>
#include <cuda_bf16.h>
#include <cstdint>

#define B_  2
#define T_  2048
#define D_  2048
#define H_  16
#define HD_ 128

// Scratch (no cudaMalloc allowed): pre-split bf16 QKV (hi/lo) + attention out
#define QKVN ((size_t)B_ * H_ * T_ * HD_)
__device__ __nv_bfloat16 g_qh[QKVN], g_ql[QKVN];
__device__ __nv_bfloat16 g_kh[QKVN], g_kl[QKVN];
__device__ __nv_bfloat16 g_vh[QKVN], g_vl[QKVN];
__device__ float g_att[(size_t)B_ * T_ * D_];       // [B,T,D]

// ============================================================================
// Common HMMA helpers
// ============================================================================
__device__ __forceinline__ void mma16816(float* c, const uint32_t* a, const uint32_t* b) {
    asm volatile(
        "mma.sync.aligned.m16n8k16.row.col.f32.bf16.bf16.f32 "
        "{%0,%1,%2,%3}, {%4,%5,%6,%7}, {%8,%9}, {%0,%1,%2,%3};"
        : "+f"(c[0]), "+f"(c[1]), "+f"(c[2]), "+f"(c[3])
        : "r"(a[0]), "r"(a[1]), "r"(a[2]), "r"(a[3]), "r"(b[0]), "r"(b[1]));
}
__device__ __forceinline__ uint32_t bf2_bits(__nv_bfloat162 h) {
    uint32_t u; *reinterpret_cast<__nv_bfloat162*>(&u) = h; return u;
}
__device__ __forceinline__ void split2(float x, float y, uint32_t& hi, uint32_t& lo) {
    __nv_bfloat162 h = __floats2bfloat162_rn(x, y);
    __nv_bfloat162 l = __floats2bfloat162_rn(x - __low2float(h), y - __high2float(h));
    hi = bf2_bits(h); lo = bf2_bits(l);
}
__device__ __forceinline__ void split4(float4 v, uint2& hi, uint2& lo) {
    __nv_bfloat162 h0 = __floats2bfloat162_rn(v.x, v.y);
    __nv_bfloat162 h1 = __floats2bfloat162_rn(v.z, v.w);
    __nv_bfloat162 l0 = __floats2bfloat162_rn(v.x - __low2float(h0), v.y - __high2float(h0));
    __nv_bfloat162 l1 = __floats2bfloat162_rn(v.z - __low2float(h1), v.w - __high2float(h1));
    hi = make_uint2(bf2_bits(h0), bf2_bits(h1));
    lo = make_uint2(bf2_bits(l0), bf2_bits(l1));
}
__device__ __forceinline__ uint32_t smem_u32_of(const void* p) {
    uint32_t a;
    asm("{ .reg .u64 t; cvta.to.shared.u64 t, %1; cvt.u32.u64 %0, t; }"
        : "=r"(a) : "l"(p));
    return a;
}
__device__ __forceinline__ void ldmx4t(uint32_t* r, uint32_t saddr) {
    asm volatile("ldmatrix.sync.aligned.m8n8.x4.trans.shared.b16 {%0,%1,%2,%3}, [%4];"
                 : "=r"(r[0]), "=r"(r[1]), "=r"(r[2]), "=r"(r[3]) : "r"(saddr));
}
__device__ __forceinline__ void ldmx4(uint32_t* r, uint32_t saddr) {
    asm volatile("ldmatrix.sync.aligned.m8n8.x4.shared.b16 {%0,%1,%2,%3}, [%4];"
                 : "=r"(r[0]), "=r"(r[1]), "=r"(r[2]), "=r"(r[3]) : "r"(saddr));
}
__device__ __forceinline__ void cp16(uint32_t d, const void* s) {
    asm volatile("cp.async.cg.shared.global [%0], [%1], 16;" :: "r"(d), "l"(s) : "memory");
}
#define CP_COMMIT() asm volatile("cp.async.commit_group;" ::: "memory")
#define CP_WAIT0()  asm volatile("cp.async.wait_group 0;" ::: "memory")

// ============================================================================
// bf16x3 NT GEMM. MODE: 1 = +bias plain f32 out; 2 = split-QKV epilogue
// (writes pre-split bf16 hi/lo Q/K/V in [B,H,T,HD], Q pre-scaled).
// Compute path identical to R6/R8 (proven tensor=54%).
// ============================================================================
#define KC      16
#define AROW_P  24
#define A_SUB   (256 * AROW_P)
#define B_SUB   (128 * AROW_P)
#define STAGE_ELEMS (2 * A_SUB + 2 * B_SUB)
#define GEMM_SMEM_BYTES (2 * STAGE_ELEMS * 2)

__device__ __forceinline__ void split_sts(__nv_bfloat16* hi, __nv_bfloat16* lo,
                                          int idx, float4 v) {
    uint2 hv, lv;
    split4(v, hv, lv);
    *reinterpret_cast<uint2*>(hi + idx) = hv;
    *reinterpret_cast<uint2*>(lo + idx) = lv;
}

template <int MODE>
__global__ __launch_bounds__(256)
void gemm_hmma(const float* __restrict__ A, const float* __restrict__ Bw,
               const float* __restrict__ bias, float* __restrict__ C,
               __nv_bfloat16* __restrict__ qh_o, __nv_bfloat16* __restrict__ ql_o,
               __nv_bfloat16* __restrict__ kh_o, __nv_bfloat16* __restrict__ kl_o,
               __nv_bfloat16* __restrict__ vh_o, __nv_bfloat16* __restrict__ vl_o,
               int M, int N, int K)
{
    extern __shared__ __nv_bfloat16 smem[];

    const int tid = threadIdx.x;
    const int wid = tid >> 5;
    const int lid = tid & 31;
    const int gid = lid >> 2;
    const int tig = lid & 3;
    const int wm  = wid >> 1;
    const int wn  = wid & 1;
    const int m0  = blockIdx.y * 256;
    const int n0  = blockIdx.x * 128;

    const float* Ab = A  + (size_t)m0 * K;
    const float* Bb = Bw + (size_t)n0 * K;

    const int arow0 = tid >> 2;
    const int ac4   = (tid & 3) * 4;

    float acc[4][8][4];
#pragma unroll
    for (int i = 0; i < 4; i++)
#pragma unroll
        for (int j = 0; j < 8; j++)
#pragma unroll
            for (int r = 0; r < 4; r++) acc[i][j][r] = 0.f;

    const int NC = K / KC;
    float4 areg[4], breg[2];

#pragma unroll
    for (int u = 0; u < 4; u++)
        areg[u] = *(const float4*)(Ab + (size_t)(arow0 + u * 64) * K + ac4);
#pragma unroll
    for (int u = 0; u < 2; u++)
        breg[u] = *(const float4*)(Bb + (size_t)(arow0 + u * 64) * K + ac4);
    {
        __nv_bfloat16* AH = smem;
        __nv_bfloat16* AL = smem + A_SUB;
        __nv_bfloat16* BH = smem + 2 * A_SUB;
        __nv_bfloat16* BL = smem + 2 * A_SUB + B_SUB;
#pragma unroll
        for (int u = 0; u < 4; u++)
            split_sts(AH, AL, (arow0 + u * 64) * AROW_P + ac4, areg[u]);
#pragma unroll
        for (int u = 0; u < 2; u++)
            split_sts(BH, BL, (arow0 + u * 64) * AROW_P + ac4, breg[u]);
    }
    __syncthreads();

    for (int kc = 0; kc < NC; kc++) {
        const int s = kc & 1;
        const int k0n = (kc + 1) * KC;

        if (kc + 1 < NC) {
#pragma unroll
            for (int u = 0; u < 4; u++)
                areg[u] = *(const float4*)(Ab + (size_t)(arow0 + u * 64) * K + k0n + ac4);
#pragma unroll
            for (int u = 0; u < 2; u++)
                breg[u] = *(const float4*)(Bb + (size_t)(arow0 + u * 64) * K + k0n + ac4);
        }

        const __nv_bfloat16* AH = smem + s * STAGE_ELEMS;
        const __nv_bfloat16* AL = AH + A_SUB;
        const __nv_bfloat16* BH = AH + 2 * A_SUB;
        const __nv_bfloat16* BL = AH + 2 * A_SUB + B_SUB;
        const int cc = tig * 2;

        uint32_t ah[4][4], al[4][4];
#pragma unroll
        for (int mt = 0; mt < 4; mt++) {
            int r0 = wm * 64 + mt * 16 + gid;
            ah[mt][0] = *(const uint32_t*)(AH + r0 * AROW_P + cc);
            ah[mt][1] = *(const uint32_t*)(AH + (r0 + 8) * AROW_P + cc);
            ah[mt][2] = *(const uint32_t*)(AH + r0 * AROW_P + cc + 8);
            ah[mt][3] = *(const uint32_t*)(AH + (r0 + 8) * AROW_P + cc + 8);
            al[mt][0] = *(const uint32_t*)(AL + r0 * AROW_P + cc);
            al[mt][1] = *(const uint32_t*)(AL + (r0 + 8) * AROW_P + cc);
            al[mt][2] = *(const uint32_t*)(AL + r0 * AROW_P + cc + 8);
            al[mt][3] = *(const uint32_t*)(AL + (r0 + 8) * AROW_P + cc + 8);
        }
#pragma unroll
        for (int nt = 0; nt < 8; nt++) {
            int rn = wn * 64 + nt * 8 + gid;
            uint32_t bh[2], bl[2];
            bh[0] = *(const uint32_t*)(BH + rn * AROW_P + cc);
            bh[1] = *(const uint32_t*)(BH + rn * AROW_P + cc + 8);
            bl[0] = *(const uint32_t*)(BL + rn * AROW_P + cc);
            bl[1] = *(const uint32_t*)(BL + rn * AROW_P + cc + 8);
#pragma unroll
            for (int mt = 0; mt < 4; mt++) {
                mma16816(acc[mt][nt], ah[mt], bh);
                mma16816(acc[mt][nt], ah[mt], bl);
                mma16816(acc[mt][nt], al[mt], bh);
            }
        }

        __syncthreads();
        if (kc + 1 < NC) {
            __nv_bfloat16* AHn = smem + (s ^ 1) * STAGE_ELEMS;
            __nv_bfloat16* ALn = AHn + A_SUB;
            __nv_bfloat16* BHn = AHn + 2 * A_SUB;
            __nv_bfloat16* BLn = AHn + 2 * A_SUB + B_SUB;
#pragma unroll
            for (int u = 0; u < 4; u++)
                split_sts(AHn, ALn, (arow0 + u * 64) * AROW_P + ac4, areg[u]);
#pragma unroll
            for (int u = 0; u < 2; u++)
                split_sts(BHn, BLn, (arow0 + u * 64) * AROW_P + ac4, breg[u]);
            __syncthreads();
        }
    }

    if (MODE == 1) {
#pragma unroll
        for (int mt = 0; mt < 4; mt++) {
            int m = m0 + wm * 64 + mt * 16 + gid;
#pragma unroll
            for (int nt = 0; nt < 8; nt++) {
                int n = n0 + wn * 64 + nt * 8 + tig * 2;
                float2 v0 = make_float2(acc[mt][nt][0], acc[mt][nt][1]);
                float2 v1 = make_float2(acc[mt][nt][2], acc[mt][nt][3]);
                float b0 = bias[n], b1 = bias[n + 1];
                v0.x += b0; v0.y += b1;
                v1.x += b0; v1.y += b1;
                *(float2*)(C + (size_t)m * N + n)       = v0;
                *(float2*)(C + (size_t)(m + 8) * N + n) = v1;
            }
        }
    } else {
        // split-QKV epilogue: write bf16 hi/lo into [B,H,T,HD]; Q pre-scaled
        const float qscale = 0.08838834764831845f;   // 1/sqrt(128)
#pragma unroll
        for (int mt = 0; mt < 4; mt++) {
            int m = m0 + wm * 64 + mt * 16 + gid;
            int bb = m >> 11, tt = m & 2047;
#pragma unroll
            for (int nt = 0; nt < 8; nt++) {
                int n = n0 + wn * 64 + nt * 8 + tig * 2;
                int tens = n >> 11;
                int dcol = n & 2047;
                int hh = dcol >> 7, hd = dcol & 127;
                size_t idx = (((size_t)(bb * 16 + hh)) * 2048 + tt) * 128 + hd;
                float sc = (tens == 0) ? qscale : 1.0f;
                uint32_t h0, l0, h1, l1;
                split2(acc[mt][nt][0] * sc, acc[mt][nt][1] * sc, h0, l0);
                split2(acc[mt][nt][2] * sc, acc[mt][nt][3] * sc, h1, l1);
                __nv_bfloat16 *dh, *dl;
                if (tens == 0)      { dh = qh_o; dl = ql_o; }
                else if (tens == 1) { dh = kh_o; dl = kl_o; }
                else                { dh = vh_o; dl = vl_o; }
                *(uint32_t*)(dh + idx) = h0;
                *(uint32_t*)(dl + idx) = l0;
                *(uint32_t*)(dh + idx + 8 * 128) = h1;
                *(uint32_t*)(dl + idx + 8 * 128) = l1;
            }
        }
    }
}

// ============================================================================
// HMMA causal flash attention v2 — consumes pre-split bf16 Q/K/V.
// CTA: 8 warps, 128 q-rows of one (b,h). cp.async double-buffered K/V tiles.
// S b-frags via ldmatrix.x4; PV via ldmatrix.x4.trans. No conversion ALU.
// ============================================================================
#define AST 152                            // bf16 row stride (conflict-free)
#define STG (64 * AST)                     // elems per array per stage
#define FL_STAGE (4 * STG)                 // elems per stage
#define FL_SMEM_BYTES (2 * FL_STAGE * 2)   // 155648 B

__global__ __launch_bounds__(256)
void flash_hmma2(const __nv_bfloat16* __restrict__ QH, const __nv_bfloat16* __restrict__ QL,
                 const __nv_bfloat16* __restrict__ KHg, const __nv_bfloat16* __restrict__ KLg,
                 const __nv_bfloat16* __restrict__ VHg, const __nv_bfloat16* __restrict__ VLg,
                 float* __restrict__ out)
{
    extern __shared__ __nv_bfloat16 asm_[];
    const uint32_t smb = smem_u32_of(asm_);

    const int qb  = blockIdx.x;
    const int bh  = blockIdx.y;
    const int b   = bh >> 4;
    const int h   = bh & 15;
    const int tid = threadIdx.x;
    const int wid = tid >> 5;
    const int lid = tid & 31;
    const int gid = lid >> 2;
    const int tig = lid & 3;

    const size_t hb = (size_t)bh * T_ * HD_;   // [B,H,T,HD] head base

    // ---- Q fragments (pre-scaled, pre-split): straight uint32 loads
    const int r0 = qb * 128 + wid * 16 + gid;
    uint32_t qh[8][4], ql[8][4];
    {
        const __nv_bfloat16* q0h = QH + hb + (size_t)r0 * HD_;
        const __nv_bfloat16* q1h = QH + hb + (size_t)(r0 + 8) * HD_;
        const __nv_bfloat16* q0l = QL + hb + (size_t)r0 * HD_;
        const __nv_bfloat16* q1l = QL + hb + (size_t)(r0 + 8) * HD_;
#pragma unroll
        for (int kc = 0; kc < 8; kc++) {
            int c = kc * 16 + 2 * tig;
            qh[kc][0] = *(const uint32_t*)(q0h + c);
            qh[kc][1] = *(const uint32_t*)(q1h + c);
            qh[kc][2] = *(const uint32_t*)(q0h + c + 8);
            qh[kc][3] = *(const uint32_t*)(q1h + c + 8);
            ql[kc][0] = *(const uint32_t*)(q0l + c);
            ql[kc][1] = *(const uint32_t*)(q1l + c);
            ql[kc][2] = *(const uint32_t*)(q0l + c + 8);
            ql[kc][3] = *(const uint32_t*)(q1l + c + 8);
        }
    }

    float m0 = -1e30f, m1 = -1e30f, l0 = 0.f, l1 = 0.f;
    float o[16][4];
#pragma unroll
    for (int i = 0; i < 16; i++)
#pragma unroll
        for (int r = 0; r < 4; r++) o[i][r] = 0.f;

    // loader geometry: threads 0-63->KH, 64-127->KL, 128-191->VH, 192-255->VL
    const int lu = tid & 63;
    const int la = tid >> 6;
    const __nv_bfloat16* lg =
        (la == 0) ? (KHg + hb) : (la == 1) ? (KLg + hb)
      : (la == 2) ? (VHg + hb) : (VLg + hb);

    // ldmatrix lane offsets
    const uint32_t lmoff = (uint32_t)(((lid & 7) * AST + (lid >> 3) * 8) * 2); // S b-frags
    const uint32_t voff  = (uint32_t)(((lid & 15) * AST + (lid >> 4) * 8) * 2); // PV trans

    const int ntiles = 2 * qb + 2;

    // prefetch tile 0 -> stage 0
    {
        uint32_t sd = smb + (uint32_t)(la * STG) * 2;
#pragma unroll
        for (int i = 0; i < 16; i++) {
            int cid = lu + 64 * i;
            int row = cid >> 4, col = cid & 15;
            cp16(sd + (uint32_t)(row * AST + col * 8) * 2,
                 lg + (size_t)row * HD_ + col * 8);
        }
    }
    CP_COMMIT();

    for (int kb = 0; kb < ntiles; kb++) {
        CP_WAIT0();
        __syncthreads();

        if (kb + 1 < ntiles) {
            uint32_t sd = smb + (uint32_t)(((kb + 1) & 1) * FL_STAGE + la * STG) * 2;
            const __nv_bfloat16* gs = lg + (size_t)((kb + 1) * 64) * HD_;
#pragma unroll
            for (int i = 0; i < 16; i++) {
                int cid = lu + 64 * i;
                int row = cid >> 4, col = cid & 15;
                cp16(sd + (uint32_t)(row * AST + col * 8) * 2,
                     gs + (size_t)row * HD_ + col * 8);
            }
            CP_COMMIT();
        }

        // per-warp skip of fully-masked diagonal tiles
        if (kb * 64 > qb * 128 + wid * 16 + 15) continue;

        const int st = kb & 1;
        const uint32_t kh_s = smb + (uint32_t)(st * FL_STAGE) * 2;
        const uint32_t kl_s = kh_s + (uint32_t)STG * 2;
        const uint32_t vh_s = kh_s + (uint32_t)(2 * STG) * 2;
        const uint32_t vl_s = kh_s + (uint32_t)(3 * STG) * 2;

        // ---- S = Q K^T  (b-frags via ldmatrix.x4: two kc per load)
        float s[8][4];
#pragma unroll
        for (int nt = 0; nt < 8; nt++)
#pragma unroll
            for (int r = 0; r < 4; r++) s[nt][r] = 0.f;

#pragma unroll
        for (int kcp = 0; kcp < 4; kcp++) {
#pragma unroll
            for (int nt = 0; nt < 8; nt++) {
                uint32_t off = (uint32_t)(nt * 8 * AST * 2 + kcp * 64) + lmoff;
                uint32_t bh4[4], bl4[4];
                ldmx4(bh4, kh_s + off);
                ldmx4(bl4, kl_s + off);
                mma16816(s[nt], qh[2 * kcp],     bh4);
                mma16816(s[nt], qh[2 * kcp],     bl4);
                mma16816(s[nt], ql[2 * kcp],     bh4);
                mma16816(s[nt], qh[2 * kcp + 1], bh4 + 2);
                mma16816(s[nt], qh[2 * kcp + 1], bl4 + 2);
                mma16816(s[nt], ql[2 * kcp + 1], bh4 + 2);
            }
        }

        // ---- causal mask (warp-uniform branch)
        if (kb * 64 + 63 > qb * 128 + wid * 16) {
            const int rr0 = r0, rr1 = r0 + 8;
#pragma unroll
            for (int nt = 0; nt < 8; nt++) {
                int c0 = kb * 64 + nt * 8 + 2 * tig;
                int c1 = c0 + 1;
                if (c0 > rr0) s[nt][0] = -1e30f;
                if (c1 > rr0) s[nt][1] = -1e30f;
                if (c0 > rr1) s[nt][2] = -1e30f;
                if (c1 > rr1) s[nt][3] = -1e30f;
            }
        }

        // ---- online softmax (fragment-level; quad shfl reductions)
        float mx0 = -1e30f, mx1 = -1e30f;
#pragma unroll
        for (int nt = 0; nt < 8; nt++) {
            mx0 = fmaxf(mx0, fmaxf(s[nt][0], s[nt][1]));
            mx1 = fmaxf(mx1, fmaxf(s[nt][2], s[nt][3]));
        }
        mx0 = fmaxf(mx0, __shfl_xor_sync(0xFFFFFFFF, mx0, 1));
        mx0 = fmaxf(mx0, __shfl_xor_sync(0xFFFFFFFF, mx0, 2));
        mx1 = fmaxf(mx1, __shfl_xor_sync(0xFFFFFFFF, mx1, 1));
        mx1 = fmaxf(mx1, __shfl_xor_sync(0xFFFFFFFF, mx1, 2));
        float mn0 = fmaxf(m0, mx0), mn1 = fmaxf(m1, mx1);
        float a0 = __expf(m0 - mn0), a1 = __expf(m1 - mn1);
        m0 = mn0; m1 = mn1;

        float ps0 = 0.f, ps1 = 0.f;
#pragma unroll
        for (int nt = 0; nt < 8; nt++) {
            s[nt][0] = __expf(s[nt][0] - mn0); ps0 += s[nt][0];
            s[nt][1] = __expf(s[nt][1] - mn0); ps0 += s[nt][1];
            s[nt][2] = __expf(s[nt][2] - mn1); ps1 += s[nt][2];
            s[nt][3] = __expf(s[nt][3] - mn1); ps1 += s[nt][3];
        }
        ps0 += __shfl_xor_sync(0xFFFFFFFF, ps0, 1);
        ps0 += __shfl_xor_sync(0xFFFFFFFF, ps0, 2);
        ps1 += __shfl_xor_sync(0xFFFFFFFF, ps1, 1);
        ps1 += __shfl_xor_sync(0xFFFFFFFF, ps1, 2);
        l0 = l0 * a0 + ps0;
        l1 = l1 * a1 + ps1;

#pragma unroll
        for (int nt = 0; nt < 16; nt++) {
            o[nt][0] *= a0; o[nt][1] *= a0;
            o[nt][2] *= a1; o[nt][3] *= a1;
        }

        // ---- O += P V  (P a-frags from S accs; V b-frags via ldmatrix.trans)
#pragma unroll
        for (int kt = 0; kt < 4; kt++) {
            uint32_t aph[4], apl[4];
            split2(s[2 * kt][0],     s[2 * kt][1],     aph[0], apl[0]);
            split2(s[2 * kt][2],     s[2 * kt][3],     aph[1], apl[1]);
            split2(s[2 * kt + 1][0], s[2 * kt + 1][1], aph[2], apl[2]);
            split2(s[2 * kt + 1][2], s[2 * kt + 1][3], aph[3], apl[3]);
            const uint32_t ktoff = (uint32_t)(kt * 16 * AST * 2);
#pragma unroll
            for (int ntp = 0; ntp < 8; ntp++) {
                uint32_t vh4[4], vl4[4];
                uint32_t off = ktoff + (uint32_t)(ntp * 32) + voff;
                ldmx4t(vh4, vh_s + off);
                ldmx4t(vl4, vl_s + off);
                mma16816(o[2 * ntp],     aph, vh4);
                mma16816(o[2 * ntp],     aph, vl4);
                mma16816(o[2 * ntp],     apl, vh4);
                mma16816(o[2 * ntp + 1], aph, vh4 + 2);
                mma16816(o[2 * ntp + 1], aph, vl4 + 2);
                mma16816(o[2 * ntp + 1], apl, vh4 + 2);
            }
        }
    }

    // ---- normalize + write [B,T,D]
    float il0 = 1.f / l0, il1 = 1.f / l1;
    float* o0 = out + ((size_t)b * T_ + r0) * D_ + h * HD_;
    float* o1 = out + ((size_t)b * T_ + r0 + 8) * D_ + h * HD_;
#pragma unroll
    for (int nt = 0; nt < 16; nt++) {
        *(float2*)(o0 + nt * 8 + 2 * tig) = make_float2(o[nt][0] * il0, o[nt][1] * il0);
        *(float2*)(o1 + nt * 8 + 2 * tig) = make_float2(o[nt][2] * il1, o[nt][3] * il1);
    }
}

// ---------------------------------------------------------------------------
extern "C" void kernel_launch(void* const* d_in, const int* in_sizes, int n_in,
                              void* d_out, int out_size)
{
    (void)in_sizes; (void)n_in; (void)out_size;
    const float* x    = (const float*)d_in[0];   // [B,T,D]
    const float* wqkv = (const float*)d_in[2];   // [3D,D]
    const float* wout = (const float*)d_in[3];   // [D,D]
    const float* bout = (const float*)d_in[4];   // [D]
    float* outp = (float*)d_out;

    float* att_p;
    __nv_bfloat16 *qh_p, *ql_p, *kh_p, *kl_p, *vh_p, *vl_p;
    cudaGetSymbolAddress((void**)&att_p, g_att);
    cudaGetSymbolAddress((void**)&qh_p, g_qh);
    cudaGetSymbolAddress((void**)&ql_p, g_ql);
    cudaGetSymbolAddress((void**)&kh_p, g_kh);
    cudaGetSymbolAddress((void**)&kl_p, g_kl);
    cudaGetSymbolAddress((void**)&vh_p, g_vh);
    cudaGetSymbolAddress((void**)&vl_p, g_vl);

    cudaFuncSetAttribute(gemm_hmma<1>,
                         cudaFuncAttributeMaxDynamicSharedMemorySize, GEMM_SMEM_BYTES);
    cudaFuncSetAttribute(gemm_hmma<2>,
                         cudaFuncAttributeMaxDynamicSharedMemorySize, GEMM_SMEM_BYTES);
    cudaFuncSetAttribute(flash_hmma2,
                         cudaFuncAttributeMaxDynamicSharedMemorySize, FL_SMEM_BYTES);

    // 1) QKV projection + fused split/scale epilogue
    dim3 g1((3 * D_) / 128, (B_ * T_) / 256);
    gemm_hmma<2><<<g1, 256, GEMM_SMEM_BYTES>>>(x, wqkv, nullptr, nullptr,
                                               qh_p, ql_p, kh_p, kl_p, vh_p, vl_p,
                                               B_ * T_, 3 * D_, D_);

    // 2) causal flash attention (pre-split bf16, cp.async pipelined)
    dim3 g2(T_ / 128, B_ * H_);
    flash_hmma2<<<g2, 256, FL_SMEM_BYTES>>>(qh_p, ql_p, kh_p, kl_p, vh_p, vl_p, att_p);

    // 3) output projection + bias
    dim3 g3(D_ / 128, (B_ * T_) / 256);
    gemm_hmma<1><<<g3, 256, GEMM_SMEM_BYTES>>>(att_p, wout, bout, outp,
                                               nullptr, nullptr, nullptr, nullptr,
                                               nullptr, nullptr,
                                               B_ * T_, D_, D_);
}